// round 2
// baseline (speedup 1.0000x reference)
#include <cuda_runtime.h>
#include <cstdint>

// ---------------------------------------------------------------------------
// AllPassMORRCirculantConv2d  (B=8, Cin=32, H=W=64, K=3, S=1, P=1, Cout=64)
// WIN=288, MB=8 -> Q=36, P=8, OUT_PAD=64. Gain = sqrt(100/36).
//
// Math: per pixel, per (p,q,k):
//   phase = sum_j inten[q*8+j] * w[p][q][(k-j)&7]       (circular conv, n=8)
//   tr    = (K1 - g*cos phase) / (K2 - g*cos phase),  g=2AR
//   out[p*8+k] = sum_q scale[q]*tr
// Using tr = 1 + D/(K2 - g cos), D = K1-K2, and sum_q scale[q] == 0 (Q even):
//   out[p*8+k] = sum_q (scale[q]*D) * rcp(K2 - g*cos(phase))
// ---------------------------------------------------------------------------

#define AA 0.8578
#define RR 0.8985
__device__ __constant__ float c_dummy; // keep nvcc happy about empty cmem use

static constexpr float G2f = (float)(2.0 * AA * RR);                       // 2AR
static constexpr float K2f = (float)(1.0 + (AA * RR) * (AA * RR));         // 1+(AR)^2
static constexpr float Df  = (float)((AA * AA + RR * RR) - 1.0
                                     - (AA * RR) * (AA * RR));             // K1-K2 (<0)
static constexpr float GAINf = 1.6666666666666667f;                        // sqrt(100/36)

// Padded, squared, gain-scaled input: [8][32][66][66]
#define PH 66
#define PW 66
#define NPAD (8 * 32 * PH * PW)
__device__ float g_sq[NPAD];

// ---------------- Kernel 1: pad + square + gain ----------------------------
__global__ void prep_kernel(const float* __restrict__ x) {
    int i = blockIdx.x * blockDim.x + threadIdx.x;
    if (i >= NPAD) return;
    int px = i % PW;
    int t  = i / PW;
    int py = t % PH;
    int bc = t / PH;           // b*32 + c
    float v = 0.0f;
    if (px >= 1 && px <= 64 && py >= 1 && py <= 64) {
        float u = x[bc * 4096 + (py - 1) * 64 + (px - 1)];
        v = u * u * GAINf;
    }
    g_sq[i] = v;
}

// ---------------- Kernel 2: main -------------------------------------------
__global__ __launch_bounds__(128, 4)
void morr_main_kernel(const float* __restrict__ weight,   // [8][36][8]
                      const float* __restrict__ mscale,   // [19]
                      float* __restrict__ out)            // [8][64][64][64]
{
    __shared__ float sw[8 * 36 * 8];     // weights
    __shared__ float ss2[36];            // scale[q]*D
    __shared__ int   stab[288];          // window offset table into g_sq

    const int tid = threadIdx.x;
    for (int i = tid; i < 2304; i += 128) sw[i] = weight[i];
    for (int i = tid; i < 36; i += 128) {
        float s = (i < 18) ? mscale[i] : -mscale[i - 18];
        ss2[i] = s * Df;
    }
    for (int w = tid; w < 288; w += 128) {
        int c = w / 9, r = w % 9;
        stab[w] = c * (PH * PW) + (r / 3) * PW + (r % 3);
    }
    __syncthreads();

    const int pix = blockIdx.x * 128 + tid;   // 0..32767
    const int b   = pix >> 12;
    const int yx  = pix & 4095;
    const int y   = yx >> 6;
    const int x   = yx & 63;

    const float* base = g_sq + b * (32 * PH * PW) + y * PW + x;

    float acc[64];
#pragma unroll
    for (int i = 0; i < 64; i++) acc[i] = 0.0f;

    for (int q = 0; q < 36; q++) {
        float inten[8];
#pragma unroll
        for (int t = 0; t < 8; t++) inten[t] = base[stab[q * 8 + t]];
        const float s2 = ss2[q];

#pragma unroll
        for (int p = 0; p < 8; p++) {
            const float4* wp = reinterpret_cast<const float4*>(&sw[p * 288 + q * 8]);
            float4 wa = wp[0];
            float4 wb = wp[1];
            float w8[8] = {wa.x, wa.y, wa.z, wa.w, wb.x, wb.y, wb.z, wb.w};

#pragma unroll
            for (int k = 0; k < 8; k++) {
                float ph = 0.0f;
#pragma unroll
                for (int j = 0; j < 8; j++)
                    ph = fmaf(inten[j], w8[(k - j) & 7], ph);
                float ct  = __cosf(ph);
                float den = fmaf(-G2f, ct, K2f);
                float r;
                asm("rcp.approx.f32 %0, %1;" : "=f"(r) : "f"(den));
                acc[p * 8 + k] = fmaf(s2, r, acc[p * 8 + k]);
            }
        }
    }

    float* op = out + (b * 64) * 4096 + y * 64 + x;
#pragma unroll
    for (int oc = 0; oc < 64; oc++) op[oc * 4096] = acc[oc];
}

// ---------------- launch ----------------------------------------------------
extern "C" void kernel_launch(void* const* d_in, const int* in_sizes, int n_in,
                              void* d_out, int out_size)
{
    const float* x   = (const float*)d_in[0];   // (8,32,64,64)
    const float* wgt = (const float*)d_in[1];   // (8,36,8)
    const float* ms  = (const float*)d_in[2];   // (19,)
    float* out = (float*)d_out;                 // (8,64,64,64)

    prep_kernel<<<(NPAD + 255) / 256, 256>>>(x);
    morr_main_kernel<<<256, 128>>>(wgt, ms, out);
}

// round 5
// speedup vs baseline: 1.0263x; 1.0263x over previous
#include <cuda_runtime.h>
#include <cstdint>

// ---------------------------------------------------------------------------
// AllPassMORRCirculantConv2d  (B=8, Cin=32, H=W=64, K=3, S=1, P=1, Cout=64)
// WIN=288, MB=8 -> Q=36, P=8, OUT_PAD=64. Gain = sqrt(100/36).
//
// out[p*8+k] = sum_q (scale[q]*D) * rcp(K2 - 2AR*cos(phase_{p,q,k}))
// phase_{p,q,k} = sum_j inten[q*8+j] * w[p][q][(k-j)&7]   (circular conv n=8)
//
// R2: 4-way P-split (2 p's / thread) for occupancy + packed fma.rn.f32x2
//     for the circulant MACs (weight pairs {w[m], w[(m+1)&7]} precomputed).
// ---------------------------------------------------------------------------

#define AA 0.8578
#define RR 0.8985

static constexpr float G2f = (float)(2.0 * AA * RR);                   // 2AR
static constexpr float K2f = (float)(1.0 + (AA * RR) * (AA * RR));     // 1+(AR)^2
static constexpr float Df  = (float)((AA * AA + RR * RR) - 1.0
                                     - (AA * RR) * (AA * RR));         // K1-K2
static constexpr float GAINf = 1.6666666666666667f;                    // sqrt(100/36)

// Padded, squared, gain-scaled input: [8][32][66][66]
#define PH 66
#define PW 66
#define NPAD (8 * 32 * PH * PW)
__device__ float g_sq[NPAD];

// ---------------- packed f32x2 helpers -------------------------------------
__device__ __forceinline__ unsigned long long pack2(float lo, float hi) {
    unsigned long long r;
    asm("mov.b64 %0, {%1, %2};" : "=l"(r) : "f"(lo), "f"(hi));
    return r;
}
__device__ __forceinline__ void unpack2(unsigned long long v, float& lo, float& hi) {
    asm("mov.b64 {%0, %1}, %2;" : "=f"(lo), "=f"(hi) : "l"(v));
}
__device__ __forceinline__ unsigned long long fma2(unsigned long long a,
                                                   unsigned long long b,
                                                   unsigned long long c) {
    unsigned long long d;
    asm("fma.rn.f32x2 %0, %1, %2, %3;" : "=l"(d) : "l"(a), "l"(b), "l"(c));
    return d;
}

// ---------------- Kernel 1: pad + square + gain ----------------------------
__global__ void prep_kernel(const float* __restrict__ x) {
    int i = blockIdx.x * blockDim.x + threadIdx.x;
    if (i >= NPAD) return;
    int px = i % PW;
    int t  = i / PW;
    int py = t % PH;
    int bc = t / PH;
    float v = 0.0f;
    if (px >= 1 && px <= 64 && py >= 1 && py <= 64) {
        float u = x[bc * 4096 + (py - 1) * 64 + (px - 1)];
        v = u * u * GAINf;
    }
    g_sq[i] = v;
}

// ---------------- Kernel 2: main -------------------------------------------
// block = 256 threads: 64 pixels x 4 p-groups (2 p's each). grid = 512.
__global__ __launch_bounds__(256, 3)
void morr_main_kernel(const float* __restrict__ weight,   // [8][36][8]
                      const float* __restrict__ mscale,   // [19]
                      float* __restrict__ out)            // [8][64][64][64]
{
    // sw2[p][q][m] = {w[p][q][m], w[p][q][(m+1)&7]}
    __shared__ float2 sw2[8 * 36 * 8];
    __shared__ float  ss2[36];           // scale[q] * D
    __shared__ int    stab[288];         // window offsets into g_sq

    const int tid = threadIdx.x;
    for (int i = tid; i < 2304; i += 256) {
        int m    = i & 7;
        int base = i - m;                // (p*36+q)*8
        float a = weight[base + m];
        float b = weight[base + ((m + 1) & 7)];
        sw2[i] = make_float2(a, b);
    }
    for (int i = tid; i < 36; i += 256) {
        float s = (i < 18) ? mscale[i] : -mscale[i - 18];
        ss2[i] = s * Df;
    }
    for (int w = tid; w < 288; w += 256) {
        int c = w / 9, r = w % 9;
        stab[w] = c * (PH * PW) + (r / 3) * PW + (r % 3);
    }
    __syncthreads();

    const int pixl = tid & 63;
    const int pgrp = tid >> 6;                      // 0..3 -> p in {2*pgrp, 2*pgrp+1}
    const int pix  = blockIdx.x * 64 + pixl;        // 0..32767
    const int b    = pix >> 12;
    const int yx   = pix & 4095;
    const int y    = yx >> 6;
    const int x    = yx & 63;

    const float* base = g_sq + b * (32 * PH * PW) + y * PW + x;

    float acc[16];
#pragma unroll
    for (int i = 0; i < 16; i++) acc[i] = 0.0f;

    for (int q = 0; q < 36; q++) {
        unsigned long long inten2[8];
#pragma unroll
        for (int t = 0; t < 8; t++) {
            float v = base[stab[q * 8 + t]];
            inten2[t] = pack2(v, v);
        }
        const float s2 = ss2[q];

#pragma unroll
        for (int pp = 0; pp < 2; pp++) {
            const int p = pgrp * 2 + pp;
            const unsigned long long* wrow =
                reinterpret_cast<const unsigned long long*>(&sw2[(p * 36 + q) * 8]);
            unsigned long long w2[8];
#pragma unroll
            for (int m = 0; m < 8; m++) w2[m] = wrow[m];

            unsigned long long ph2[4] = {0ull, 0ull, 0ull, 0ull};
#pragma unroll
            for (int j = 0; j < 8; j++) {
#pragma unroll
                for (int kk = 0; kk < 4; kk++)
                    ph2[kk] = fma2(inten2[j], w2[(2 * kk - j) & 7], ph2[kk]);
            }

#pragma unroll
            for (int kk = 0; kk < 4; kk++) {
                float p0, p1;
                unpack2(ph2[kk], p0, p1);
                float c0 = __cosf(p0);
                float c1 = __cosf(p1);
                float d0 = fmaf(-G2f, c0, K2f);
                float d1 = fmaf(-G2f, c1, K2f);
                float r0, r1;
                asm("rcp.approx.f32 %0, %1;" : "=f"(r0) : "f"(d0));
                asm("rcp.approx.f32 %0, %1;" : "=f"(r1) : "f"(d1));
                acc[pp * 8 + 2 * kk]     = fmaf(s2, r0, acc[pp * 8 + 2 * kk]);
                acc[pp * 8 + 2 * kk + 1] = fmaf(s2, r1, acc[pp * 8 + 2 * kk + 1]);
            }
        }
    }

    float* op = out + (b * 64 + pgrp * 16) * 4096 + y * 64 + x;
#pragma unroll
    for (int oc = 0; oc < 16; oc++) op[oc * 4096] = acc[oc];
}

// ---------------- launch ----------------------------------------------------
extern "C" void kernel_launch(void* const* d_in, const int* in_sizes, int n_in,
                              void* d_out, int out_size)
{
    const float* x   = (const float*)d_in[0];   // (8,32,64,64)
    const float* wgt = (const float*)d_in[1];   // (8,36,8)
    const float* ms  = (const float*)d_in[2];   // (19,)
    float* out = (float*)d_out;                 // (8,64,64,64)

    prep_kernel<<<(NPAD + 255) / 256, 256>>>(x);
    morr_main_kernel<<<512, 256>>>(wgt, ms, out);
}